// round 1
// baseline (speedup 1.0000x reference)
#include <cuda_runtime.h>

// SimpleAttention collapses mathematically:
//   softmax over the QUERY axis means sum_q att[b,q,s] = 1 for every (b,s),
//   so mean_q(att @ v) = (1/S) * sum_s v[b,s,:] = mean_s (x[b,s,:] @ Wv + bv)
//   => out[b,k] = (mean_s x[b,s,:]) @ Wv[:,k] + bv[k]
// Only real work: one 67 MB streaming reduction over x (HBM-bound).

#define BB 8
#define SS 2048
#define DD 1024
#define DKK 512
#define NCHUNK 64
#define SCHUNK (SS / NCHUNK)   // 32
#define DSPLIT 8
#define DSEG (DD / DSPLIT)     // 128

// Scratch (no cudaMalloc allowed)
__device__ float g_partial[BB * NCHUNK * DD];   // [b][chunk][d]  2 MB
__device__ float g_part2[BB * DSPLIT * DKK];    // [b][dsplit][k] 128 KB

// ---------------------------------------------------------------------------
// k1: partial column sums of x over S-chunks.
// grid (1, NCHUNK, B), block 256. Thread t owns 4 consecutive d (float4).
// ---------------------------------------------------------------------------
__global__ void __launch_bounds__(256) k1_colsum(const float* __restrict__ x) {
    const int c = blockIdx.y;
    const int b = blockIdx.z;
    const int d = threadIdx.x * 4;

    const float4* xp = reinterpret_cast<const float4*>(
        x + ((size_t)(b * SS + c * SCHUNK)) * DD + d);

    float4 acc = make_float4(0.f, 0.f, 0.f, 0.f);
#pragma unroll 4
    for (int s = 0; s < SCHUNK; s++) {
        float4 v = xp[(size_t)s * (DD / 4)];
        acc.x += v.x; acc.y += v.y; acc.z += v.z; acc.w += v.w;
    }
    *reinterpret_cast<float4*>(g_partial + ((b * NCHUNK + c) * DD + d)) = acc;
}

// ---------------------------------------------------------------------------
// k2: reduce chunk partials to xbar for a 128-wide d segment, then compute
// the partial GEMM slice: part2[b][ds][k] = sum_{d in seg} xbar[d]*Wv[d][k].
// grid (B, DSPLIT), block 256 (each thread owns 2 consecutive k).
// ---------------------------------------------------------------------------
__global__ void __launch_bounds__(256) k2_gemm(const float* __restrict__ Wv) {
    __shared__ float xb[DSEG];
    const int b = blockIdx.x;
    const int ds = blockIdx.y;
    const int t = threadIdx.x;
    const int dbase = ds * DSEG;

    if (t < DSEG) {
        float s = 0.f;
#pragma unroll 8
        for (int c = 0; c < NCHUNK; c++)
            s += g_partial[(b * NCHUNK + c) * DD + dbase + t];
        xb[t] = s * (1.0f / (float)SS);
    }
    __syncthreads();

    const int k = t * 2;
    float2 acc = make_float2(0.f, 0.f);
#pragma unroll 8
    for (int d = 0; d < DSEG; d++) {
        const float xv = xb[d];
        const float2 w = *reinterpret_cast<const float2*>(
            Wv + (size_t)(dbase + d) * DKK + k);
        acc.x += xv * w.x;
        acc.y += xv * w.y;
    }
    *reinterpret_cast<float2*>(g_part2 + (b * DSPLIT + ds) * DKK + k) = acc;
}

// ---------------------------------------------------------------------------
// k3: sum the DSPLIT partials + bias -> final [B, DK] output.
// grid 16, block 256 -> 4096 threads, one per output element.
// ---------------------------------------------------------------------------
__global__ void __launch_bounds__(256) k3_final(const float* __restrict__ bv,
                                                float* __restrict__ out) {
    const int idx = blockIdx.x * blockDim.x + threadIdx.x;  // 0..4095
    const int b = idx / DKK;
    const int k = idx % DKK;
    float s = bv[k];
#pragma unroll
    for (int ds = 0; ds < DSPLIT; ds++)
        s += g_part2[(b * DSPLIT + ds) * DKK + k];
    out[idx] = s;
}

// ---------------------------------------------------------------------------
// Inputs (metadata order): x, Wq, bq, Wk, bk, Wv, bv
// ---------------------------------------------------------------------------
extern "C" void kernel_launch(void* const* d_in, const int* in_sizes, int n_in,
                              void* d_out, int out_size) {
    const float* x  = (const float*)d_in[0];
    const float* Wv = (const float*)d_in[5];
    const float* bv = (const float*)d_in[6];
    float* out = (float*)d_out;

    k1_colsum<<<dim3(1, NCHUNK, BB), 256>>>(x);
    k2_gemm<<<dim3(BB, DSPLIT), 256>>>(Wv);
    k3_final<<<16, 256>>>(bv, out);
}